// round 3
// baseline (speedup 1.0000x reference)
#include <cuda_runtime.h>

#define T_STEPS 8192
#define DH 2048
#define RNN_CTAS 128

typedef unsigned long long ull;

__device__ __align__(16) float g_pre[(size_t)T_STEPS * DH];
__device__ __align__(16) float g_H[(size_t)T_STEPS * DH];
// one flag per CTA, padded to a 128B L2 line each
__device__ unsigned g_flags[RNN_CTAS * 32];

__device__ __forceinline__ ull pack2(float a, float b) {
    ull r; asm("mov.b64 %0, {%1, %2};" : "=l"(r) : "f"(a), "f"(b)); return r;
}
__device__ __forceinline__ void unpack2(ull v, float& a, float& b) {
    asm("mov.b64 {%0, %1}, %2;" : "=f"(a), "=f"(b) : "l"(v));
}
__device__ __forceinline__ ull fma2(ull a, ull b, ull c) {
    ull d; asm("fma.rn.f32x2 %0, %1, %2, %3;" : "=l"(d) : "l"(a), "l"(b), "l"(c));
    return d;
}
__device__ __forceinline__ unsigned ld_acq(const unsigned* p) {
    unsigned v;
    asm volatile("ld.acquire.gpu.u32 %0, [%1];" : "=r"(v) : "l"(p) : "memory");
    return v;
}
__device__ __forceinline__ void st_rel(unsigned* p, unsigned v) {
    asm volatile("st.release.gpu.u32 [%0], %1;" :: "l"(p), "r"(v) : "memory");
}

__global__ void init_kernel(const float* __restrict__ features,
                            const float* __restrict__ caption,
                            float* __restrict__ out) {
    int i = blockIdx.x * blockDim.x + threadIdx.x;
    if (i < DH) { g_H[i] = features[i]; out[i] = caption[i]; }
    if (i < RNN_CTAS * 32) g_flags[i] = 0u;
}

// C[m,n] = sum_k A[m*lda+k]*B[n*ldb+k] + bias[n], optional sigmoid.
// BM=BN=128, BK=8, 256 thr, 8x8/thread, double-buffered, f32x2 inner loop.
template <int SIG>
__global__ void __launch_bounds__(256, 2)
sgemm_nt(const float* __restrict__ A, int lda,
         const float* __restrict__ B, int ldb,
         const float* __restrict__ bias,
         float* __restrict__ C, int ldc, int M, int K) {
    __shared__ __align__(16) ull   As[2][8][128];
    __shared__ __align__(16) float Bs[2][8][128];
    const int tid = threadIdx.x;
    const int tx = tid & 15, ty = tid >> 4;
    const int bm = blockIdx.y << 7, bn = blockIdx.x << 7;
    const int lr = tid >> 1, lc = (tid & 1) << 2;
    const float* Ap = A + (size_t)(bm + lr) * lda + lc;
    const float* Bp = B + (size_t)(bn + lr) * ldb + lc;
    const bool av = (bm + lr) < M;

    ull acc[8][4];
#pragma unroll
    for (int i = 0; i < 8; ++i)
#pragma unroll
        for (int j = 0; j < 4; ++j) acc[i][j] = 0ULL;

    float4 af = av ? *reinterpret_cast<const float4*>(Ap) : make_float4(0,0,0,0);
    float4 bf = *reinterpret_cast<const float4*>(Bp);
    As[0][lc+0][lr] = pack2(af.x, af.x); As[0][lc+1][lr] = pack2(af.y, af.y);
    As[0][lc+2][lr] = pack2(af.z, af.z); As[0][lc+3][lr] = pack2(af.w, af.w);
    Bs[0][lc+0][lr] = bf.x; Bs[0][lc+1][lr] = bf.y;
    Bs[0][lc+2][lr] = bf.z; Bs[0][lc+3][lr] = bf.w;
    __syncthreads();

    const int nIter = K >> 3;
    int buf = 0;
    for (int kt = 0; kt < nIter; ++kt) {
        const bool nxt = (kt + 1) < nIter;
        if (nxt) {
            af = av ? *reinterpret_cast<const float4*>(Ap + ((kt+1) << 3)) : make_float4(0,0,0,0);
            bf = *reinterpret_cast<const float4*>(Bp + ((kt+1) << 3));
        }
#pragma unroll
        for (int k = 0; k < 8; ++k) {
            const ulonglong2* ap2 = reinterpret_cast<const ulonglong2*>(&As[buf][k][ty << 3]);
            ulonglong2 a01 = ap2[0], a23 = ap2[1], a45 = ap2[2], a67 = ap2[3];
            const float4* bp4 = reinterpret_cast<const float4*>(&Bs[buf][k][tx << 3]);
            float4 b0 = bp4[0], b1 = bp4[1];
            ull ra[8] = {a01.x, a01.y, a23.x, a23.y, a45.x, a45.y, a67.x, a67.y};
            ull rb[4] = {pack2(b0.x, b0.y), pack2(b0.z, b0.w),
                         pack2(b1.x, b1.y), pack2(b1.z, b1.w)};
#pragma unroll
            for (int i = 0; i < 8; ++i)
#pragma unroll
                for (int j = 0; j < 4; ++j) acc[i][j] = fma2(ra[i], rb[j], acc[i][j]);
        }
        if (nxt) {
            const int nb = buf ^ 1;
            As[nb][lc+0][lr] = pack2(af.x, af.x); As[nb][lc+1][lr] = pack2(af.y, af.y);
            As[nb][lc+2][lr] = pack2(af.z, af.z); As[nb][lc+3][lr] = pack2(af.w, af.w);
            Bs[nb][lc+0][lr] = bf.x; Bs[nb][lc+1][lr] = bf.y;
            Bs[nb][lc+2][lr] = bf.z; Bs[nb][lc+3][lr] = bf.w;
        }
        __syncthreads();
        buf ^= 1;
    }

    const float4* bias4 = reinterpret_cast<const float4*>(bias + bn + (tx << 3));
    float4 bv0 = bias4[0], bv1 = bias4[1];
    float bb[8] = {bv0.x, bv0.y, bv0.z, bv0.w, bv1.x, bv1.y, bv1.z, bv1.w};
#pragma unroll
    for (int i = 0; i < 8; ++i) {
        int cm = bm + (ty << 3) + i;
        if (cm < M) {
            float o[8];
#pragma unroll
            for (int j = 0; j < 4; ++j) unpack2(acc[i][j], o[2*j], o[2*j+1]);
#pragma unroll
            for (int j = 0; j < 8; ++j) {
                float v = o[j] + bb[j];
                if (SIG) v = 1.0f / (1.0f + __expf(-v));
                o[j] = v;
            }
            float4* cp = reinterpret_cast<float4*>(C + (size_t)cm * ldc + bn + (tx << 3));
            cp[0] = make_float4(o[0], o[1], o[2], o[3]);
            cp[1] = make_float4(o[4], o[5], o[6], o[7]);
        }
    }
}

// Persistent recurrence: 128 CTAs x 512 thr, W_hh register-resident.
// CTA b owns rows [16b,16b+16). warp w: rows rg=w>>2 (4, packed in f32x2
// pairs), cols chunk=(w&3)*512 + lane*16.
// Sync: per-CTA release flags (one 128B line each) + parallel acquire polls.
__global__ void __launch_bounds__(512, 1)
rnn_kernel(const float* __restrict__ Wh) {
    const int tid = threadIdx.x;
    const int warp = tid >> 5, lane = tid & 31;
    const int rg = warp >> 2, chunk = warp & 3;
    const int rowBase = blockIdx.x << 4;
    const int colBase = (chunk << 9) + (lane << 4);

    ull w01[16], w23[16];
    {
        const float* p0 = Wh + (size_t)(rowBase + (rg << 2)) * (2 * DH) + DH + colBase;
#pragma unroll
        for (int q = 0; q < 4; ++q) {
            float4 v0 = reinterpret_cast<const float4*>(p0         )[q];
            float4 v1 = reinterpret_cast<const float4*>(p0 + 2 * DH)[q];
            float4 v2 = reinterpret_cast<const float4*>(p0 + 4 * DH)[q];
            float4 v3 = reinterpret_cast<const float4*>(p0 + 6 * DH)[q];
            w01[q*4+0] = pack2(v0.x, v1.x); w01[q*4+1] = pack2(v0.y, v1.y);
            w01[q*4+2] = pack2(v0.z, v1.z); w01[q*4+3] = pack2(v0.w, v1.w);
            w23[q*4+0] = pack2(v2.x, v3.x); w23[q*4+1] = pack2(v2.y, v3.y);
            w23[q*4+2] = pack2(v2.z, v3.z); w23[q*4+3] = pack2(v2.w, v3.w);
        }
    }

    __shared__ __align__(16) float hs[DH];
    __shared__ float part[2048];
    __shared__ float preS[16];

    for (int t = 1; t < T_STEPS; ++t) {
        // wait: h_{t-1} published by every CTA (flag[c] >= t-1)
        if (tid < RNN_CTAS) {
            const unsigned want = (unsigned)(t - 1);
            while (ld_acq(&g_flags[tid << 5]) < want) {}
        }
        __syncthreads();

        *reinterpret_cast<float4*>(&hs[tid << 2]) =
            *reinterpret_cast<const float4*>(&g_H[(size_t)(t - 1) * DH + (tid << 2)]);
        if (tid < 16) preS[tid] = g_pre[(size_t)t * DH + rowBase + tid];
        __syncthreads();

        ull acc01 = 0ULL, acc23 = 0ULL;
#pragma unroll
        for (int q = 0; q < 4; ++q) {
            float4 hv = *reinterpret_cast<const float4*>(&hs[colBase + (q << 2)]);
            ull h0 = pack2(hv.x, hv.x), h1 = pack2(hv.y, hv.y);
            ull h2 = pack2(hv.z, hv.z), h3 = pack2(hv.w, hv.w);
            acc01 = fma2(w01[q*4+0], h0, acc01); acc23 = fma2(w23[q*4+0], h0, acc23);
            acc01 = fma2(w01[q*4+1], h1, acc01); acc23 = fma2(w23[q*4+1], h1, acc23);
            acc01 = fma2(w01[q*4+2], h2, acc01); acc23 = fma2(w23[q*4+2], h2, acc23);
            acc01 = fma2(w01[q*4+3], h3, acc01); acc23 = fma2(w23[q*4+3], h3, acc23);
        }
        float a0, a1, a2, a3;
        unpack2(acc01, a0, a1); unpack2(acc23, a2, a3);
        const int rb4 = rg << 2, off = (chunk << 5) + lane;
        part[(rb4+0)*128 + off] = a0;
        part[(rb4+1)*128 + off] = a1;
        part[(rb4+2)*128 + off] = a2;
        part[(rb4+3)*128 + off] = a3;
        __syncthreads();

        float s = part[warp*128 + lane] + part[warp*128 + 32 + lane] +
                  part[warp*128 + 64 + lane] + part[warp*128 + 96 + lane];
#pragma unroll
        for (int o = 16; o > 0; o >>= 1) s += __shfl_xor_sync(0xffffffffu, s, o);
        if (lane == 0) {
            float x = s + preS[warp];
            g_H[(size_t)t * DH + rowBase + warp] = 1.0f / (1.0f + __expf(-x));
        }
        __syncthreads();

        // publish: release-store this CTA's flag (orders the 16 STGs above)
        if (tid == 0) st_rel(&g_flags[blockIdx.x << 5], (unsigned)t);
    }
}

extern "C" void kernel_launch(void* const* d_in, const int* in_sizes, int n_in,
                              void* d_out, int out_size) {
    (void)in_sizes; (void)n_in; (void)out_size;
    const float* features = (const float*)d_in[0];
    const float* caption  = (const float*)d_in[1];
    const float* W_h      = (const float*)d_in[2];
    const float* b_h      = (const float*)d_in[3];
    const float* W_o      = (const float*)d_in[4];
    const float* b_o      = (const float*)d_in[5];
    float* out = (float*)d_out;

    void *preV = nullptr, *hV = nullptr;
    cudaGetSymbolAddress(&preV, g_pre);
    cudaGetSymbolAddress(&hV, g_H);
    float* pre = (float*)preV;
    float* H   = (float*)hV;

    init_kernel<<<16, 256>>>(features, caption, out);

    dim3 grid(DH / 128, (T_STEPS - 1 + 127) / 128);  // 16 x 64
    // pre[t] = caption[t-1] @ W_hx^T + b_h, rows t=1..8191
    sgemm_nt<0><<<grid, 256>>>(caption, DH, W_h, 2 * DH, b_h,
                               pre + DH, DH, T_STEPS - 1, DH);
    // serial recurrence fills H[1..8191]
    rnn_kernel<<<RNN_CTAS, 512>>>(W_h);
    // out[t] = sigmoid(H[t] @ W_o^T + b_o), rows t=1..8191
    sgemm_nt<1><<<grid, 256>>>(H + DH, DH, W_o, DH, b_o,
                               out + DH, DH, T_STEPS - 1, DH);
}

// round 4
// speedup vs baseline: 1.1794x; 1.1794x over previous
#include <cuda_runtime.h>

#define T_STEPS 8192
#define DH 2048
#define RNN_CTAS 128
#define SENT 0xFFC00001u

typedef unsigned long long ull;

__device__ __align__(16) float g_pre[(size_t)T_STEPS * DH];
__device__ __align__(16) float g_H[(size_t)T_STEPS * DH];

__device__ __forceinline__ ull pack2(float a, float b) {
    ull r; asm("mov.b64 %0, {%1, %2};" : "=l"(r) : "f"(a), "f"(b)); return r;
}
__device__ __forceinline__ void unpack2(ull v, float& a, float& b) {
    asm("mov.b64 {%0, %1}, %2;" : "=f"(a), "=f"(b) : "l"(v));
}
__device__ __forceinline__ ull fma2(ull a, ull b, ull c) {
    ull d; asm("fma.rn.f32x2 %0, %1, %2, %3;" : "=l"(d) : "l"(a), "l"(b), "l"(c));
    return d;
}
__device__ __forceinline__ uint4 ld_rlx4(const uint4* p) {
    uint4 v;
    asm volatile("ld.relaxed.gpu.global.v4.u32 {%0,%1,%2,%3}, [%4];"
        : "=r"(v.x), "=r"(v.y), "=r"(v.z), "=r"(v.w) : "l"(p) : "memory");
    return v;
}
__device__ __forceinline__ void st_rlx(float* p, float v) {
    asm volatile("st.relaxed.gpu.global.f32 [%0], %1;" :: "l"(p), "f"(v) : "memory");
}
__device__ __forceinline__ bool has_sent(uint4 v) {
    return (v.x == SENT) | (v.y == SENT) | (v.z == SENT) | (v.w == SENT);
}

__global__ void init_kernel(const float* __restrict__ features,
                            const float* __restrict__ caption,
                            float* __restrict__ out) {
    int i = blockIdx.x * blockDim.x + threadIdx.x;
    if (i < DH) { g_H[i] = features[i]; out[i] = caption[i]; }
}

// poison H rows 1..T-1 with the sentinel
__global__ void poison_kernel() {
    uint4 s = make_uint4(SENT, SENT, SENT, SENT);
    uint4* p = reinterpret_cast<uint4*>(g_H + DH);
    const size_t n = (size_t)(T_STEPS - 1) * DH / 4;
    const size_t stride = (size_t)gridDim.x * blockDim.x;
    for (size_t k = (size_t)blockIdx.x * blockDim.x + threadIdx.x; k < n; k += stride)
        p[k] = s;
}

// C[m,n] = sum_k A[m*lda+k]*B[n*ldb+k] + bias[n], optional sigmoid.
// BM=BN=128, BK=8, 256 thr, 8x8/thread, double-buffered, f32x2 inner loop.
template <int SIG>
__global__ void __launch_bounds__(256, 2)
sgemm_nt(const float* __restrict__ A, int lda,
         const float* __restrict__ B, int ldb,
         const float* __restrict__ bias,
         float* __restrict__ C, int ldc, int M, int K) {
    __shared__ __align__(16) ull   As[2][8][128];
    __shared__ __align__(16) float Bs[2][8][128];
    const int tid = threadIdx.x;
    const int tx = tid & 15, ty = tid >> 4;
    const int bm = blockIdx.y << 7, bn = blockIdx.x << 7;
    const int lr = tid >> 1, lc = (tid & 1) << 2;
    const float* Ap = A + (size_t)(bm + lr) * lda + lc;
    const float* Bp = B + (size_t)(bn + lr) * ldb + lc;
    const bool av = (bm + lr) < M;

    ull acc[8][4];
#pragma unroll
    for (int i = 0; i < 8; ++i)
#pragma unroll
        for (int j = 0; j < 4; ++j) acc[i][j] = 0ULL;

    float4 af = av ? *reinterpret_cast<const float4*>(Ap) : make_float4(0,0,0,0);
    float4 bf = *reinterpret_cast<const float4*>(Bp);
    As[0][lc+0][lr] = pack2(af.x, af.x); As[0][lc+1][lr] = pack2(af.y, af.y);
    As[0][lc+2][lr] = pack2(af.z, af.z); As[0][lc+3][lr] = pack2(af.w, af.w);
    Bs[0][lc+0][lr] = bf.x; Bs[0][lc+1][lr] = bf.y;
    Bs[0][lc+2][lr] = bf.z; Bs[0][lc+3][lr] = bf.w;
    __syncthreads();

    const int nIter = K >> 3;
    int buf = 0;
    for (int kt = 0; kt < nIter; ++kt) {
        const bool nxt = (kt + 1) < nIter;
        if (nxt) {
            af = av ? *reinterpret_cast<const float4*>(Ap + ((kt+1) << 3)) : make_float4(0,0,0,0);
            bf = *reinterpret_cast<const float4*>(Bp + ((kt+1) << 3));
        }
#pragma unroll
        for (int k = 0; k < 8; ++k) {
            const ulonglong2* ap2 = reinterpret_cast<const ulonglong2*>(&As[buf][k][ty << 3]);
            ulonglong2 a01 = ap2[0], a23 = ap2[1], a45 = ap2[2], a67 = ap2[3];
            const float4* bp4 = reinterpret_cast<const float4*>(&Bs[buf][k][tx << 3]);
            float4 b0 = bp4[0], b1 = bp4[1];
            ull ra[8] = {a01.x, a01.y, a23.x, a23.y, a45.x, a45.y, a67.x, a67.y};
            ull rb[4] = {pack2(b0.x, b0.y), pack2(b0.z, b0.w),
                         pack2(b1.x, b1.y), pack2(b1.z, b1.w)};
#pragma unroll
            for (int i = 0; i < 8; ++i)
#pragma unroll
                for (int j = 0; j < 4; ++j) acc[i][j] = fma2(ra[i], rb[j], acc[i][j]);
        }
        if (nxt) {
            const int nb = buf ^ 1;
            As[nb][lc+0][lr] = pack2(af.x, af.x); As[nb][lc+1][lr] = pack2(af.y, af.y);
            As[nb][lc+2][lr] = pack2(af.z, af.z); As[nb][lc+3][lr] = pack2(af.w, af.w);
            Bs[nb][lc+0][lr] = bf.x; Bs[nb][lc+1][lr] = bf.y;
            Bs[nb][lc+2][lr] = bf.z; Bs[nb][lc+3][lr] = bf.w;
        }
        __syncthreads();
        buf ^= 1;
    }

    const float4* bias4 = reinterpret_cast<const float4*>(bias + bn + (tx << 3));
    float4 bv0 = bias4[0], bv1 = bias4[1];
    float bb[8] = {bv0.x, bv0.y, bv0.z, bv0.w, bv1.x, bv1.y, bv1.z, bv1.w};
#pragma unroll
    for (int i = 0; i < 8; ++i) {
        int cm = bm + (ty << 3) + i;
        if (cm < M) {
            float o[8];
#pragma unroll
            for (int j = 0; j < 4; ++j) unpack2(acc[i][j], o[2*j], o[2*j+1]);
#pragma unroll
            for (int j = 0; j < 8; ++j) {
                float v = o[j] + bb[j];
                if (SIG) v = 1.0f / (1.0f + __expf(-v));
                o[j] = v;
            }
            float4* cp = reinterpret_cast<float4*>(C + (size_t)cm * ldc + bn + (tx << 3));
            cp[0] = make_float4(o[0], o[1], o[2], o[3]);
            cp[1] = make_float4(o[4], o[5], o[6], o[7]);
        }
    }
}

// Persistent recurrence: 128 CTAs x 512 thr, W_hh register-resident.
// Sync: NO flags. Producers st.relaxed h values; consumers (warps 0-3,
// 64B/thread) poll the data words directly against a sentinel that
// arithmetic can never produce. One L2 round trip per step.
__global__ void __launch_bounds__(512, 1)
rnn_kernel(const float* __restrict__ Wh) {
    const int tid = threadIdx.x;
    const int warp = tid >> 5, lane = tid & 31;
    const int rg = warp >> 2, chunk = warp & 3;
    const int rowBase = blockIdx.x << 4;
    const int colBase = (chunk << 9) + (lane << 4);

    ull w01[16], w23[16];
    {
        const float* p0 = Wh + (size_t)(rowBase + (rg << 2)) * (2 * DH) + DH + colBase;
#pragma unroll
        for (int q = 0; q < 4; ++q) {
            float4 v0 = reinterpret_cast<const float4*>(p0         )[q];
            float4 v1 = reinterpret_cast<const float4*>(p0 + 2 * DH)[q];
            float4 v2 = reinterpret_cast<const float4*>(p0 + 4 * DH)[q];
            float4 v3 = reinterpret_cast<const float4*>(p0 + 6 * DH)[q];
            w01[q*4+0] = pack2(v0.x, v1.x); w01[q*4+1] = pack2(v0.y, v1.y);
            w01[q*4+2] = pack2(v0.z, v1.z); w01[q*4+3] = pack2(v0.w, v1.w);
            w23[q*4+0] = pack2(v2.x, v3.x); w23[q*4+1] = pack2(v2.y, v3.y);
            w23[q*4+2] = pack2(v2.z, v3.z); w23[q*4+3] = pack2(v2.w, v3.w);
        }
    }

    __shared__ __align__(16) float hs[2][DH];   // parity double-buffered
    __shared__ float part[2048];
    __shared__ float preS[2][16];

    for (int t = 1; t < T_STEPS; ++t) {
        const int pb = t & 1;

        if (warp < 4) {
            // poll 64B of h_{t-1}: 4x v4 relaxed loads, re-issue until clean
            const uint4* hp = reinterpret_cast<const uint4*>(
                &g_H[(size_t)(t - 1) * DH]) + (tid << 2);
            uint4 a, b, c, d;
            for (;;) {
                a = ld_rlx4(hp + 0); b = ld_rlx4(hp + 1);
                c = ld_rlx4(hp + 2); d = ld_rlx4(hp + 3);
                if (!(has_sent(a) | has_sent(b) | has_sent(c) | has_sent(d))) break;
            }
            uint4* o = reinterpret_cast<uint4*>(&hs[pb][tid << 4]);
            o[0] = a; o[1] = b; o[2] = c; o[3] = d;
        } else if (warp == 4 && lane < 16) {
            preS[pb][lane] = g_pre[(size_t)t * DH + rowBase + lane];
        }
        __syncthreads();

        ull acc01 = 0ULL, acc23 = 0ULL;
#pragma unroll
        for (int q = 0; q < 4; ++q) {
            float4 hv = *reinterpret_cast<const float4*>(&hs[pb][colBase + (q << 2)]);
            ull h0 = pack2(hv.x, hv.x), h1 = pack2(hv.y, hv.y);
            ull h2 = pack2(hv.z, hv.z), h3 = pack2(hv.w, hv.w);
            acc01 = fma2(w01[q*4+0], h0, acc01); acc23 = fma2(w23[q*4+0], h0, acc23);
            acc01 = fma2(w01[q*4+1], h1, acc01); acc23 = fma2(w23[q*4+1], h1, acc23);
            acc01 = fma2(w01[q*4+2], h2, acc01); acc23 = fma2(w23[q*4+2], h2, acc23);
            acc01 = fma2(w01[q*4+3], h3, acc01); acc23 = fma2(w23[q*4+3], h3, acc23);
        }
        float a0, a1, a2, a3;
        unpack2(acc01, a0, a1); unpack2(acc23, a2, a3);
        const int rb4 = rg << 2, off = (chunk << 5) + lane;
        part[(rb4+0)*128 + off] = a0;
        part[(rb4+1)*128 + off] = a1;
        part[(rb4+2)*128 + off] = a2;
        part[(rb4+3)*128 + off] = a3;
        __syncthreads();

        float s = part[warp*128 + lane] + part[warp*128 + 32 + lane] +
                  part[warp*128 + 64 + lane] + part[warp*128 + 96 + lane];
#pragma unroll
        for (int o = 16; o > 0; o >>= 1) s += __shfl_xor_sync(0xffffffffu, s, o);
        if (lane == 0) {
            float x = s + preS[pb][warp];
            st_rlx(&g_H[(size_t)t * DH + rowBase + warp],
                   1.0f / (1.0f + __expf(-x)));
        }
        // no third barrier: hs/preS are parity-buffered, part is protected
        // by the two barriers above.
    }
}

extern "C" void kernel_launch(void* const* d_in, const int* in_sizes, int n_in,
                              void* d_out, int out_size) {
    (void)in_sizes; (void)n_in; (void)out_size;
    const float* features = (const float*)d_in[0];
    const float* caption  = (const float*)d_in[1];
    const float* W_h      = (const float*)d_in[2];
    const float* b_h      = (const float*)d_in[3];
    const float* W_o      = (const float*)d_in[4];
    const float* b_o      = (const float*)d_in[5];
    float* out = (float*)d_out;

    void *preV = nullptr, *hV = nullptr;
    cudaGetSymbolAddress(&preV, g_pre);
    cudaGetSymbolAddress(&hV, g_H);
    float* pre = (float*)preV;
    float* H   = (float*)hV;

    init_kernel<<<8, 256>>>(features, caption, out);
    poison_kernel<<<1024, 256>>>();

    dim3 grid(DH / 128, (T_STEPS - 1 + 127) / 128);  // 16 x 64
    // pre[t] = caption[t-1] @ W_hx^T + b_h, rows t=1..8191
    sgemm_nt<0><<<grid, 256>>>(caption, DH, W_h, 2 * DH, b_h,
                               pre + DH, DH, T_STEPS - 1, DH);
    // serial recurrence fills H[1..8191]
    rnn_kernel<<<RNN_CTAS, 512>>>(W_h);
    // out[t] = sigmoid(H[t] @ W_o^T + b_o), rows t=1..8191
    sgemm_nt<1><<<grid, 256>>>(H + DH, DH, W_o, DH, b_o,
                               out + DH, DH, T_STEPS - 1, DH);
}